// round 2
// baseline (speedup 1.0000x reference)
#include <cuda_runtime.h>

// ---------------- problem constants ----------------
constexpr int Bn = 128;   // batch
constexpr int In = 1024;  // input features
constexpr int Hn = 4096;  // hidden
constexpr int On = 512;   // output
constexpr int Tn = 100;   // timesteps
constexpr int S1 = 4;     // k-splits for GEMM1 (K=1024 -> 256 per block)
constexpr int S2 = 32;    // k-splits for GEMM2 (K=4096 -> 128 per block)

constexpr float VDEC = 0.5f;
constexpr float VTH  = 0.3f;
constexpr float GW   = 0.3f;

// ---------------- device scratch (no allocations allowed) ----------------
__device__ float    g_x[(size_t)Tn * Bn * In];    // [T][B][I]  52.4 MB
__device__ float    g_hv[Bn * Hn];                // hidden membrane voltage
__device__ float    g_ov[Bn * On];                // output membrane voltage
__device__ float    g_p1[(size_t)S1 * Bn * Hn];   // GEMM1 split-K partials 8 MB
__device__ float    g_p2[(size_t)S2 * Bn * On];   // GEMM2 split-K partials 8 MB
__device__ unsigned g_maxh[Tn];                   // per-step global max(hv) (encoded)
__device__ unsigned g_maxo[Tn];                   // per-step global max(ov) (encoded)

// monotone float<->uint encoding so atomicMax on uint == float max
__device__ __forceinline__ unsigned enc_f(float x) {
    unsigned u = __float_as_uint(x);
    return (u & 0x80000000u) ? ~u : (u | 0x80000000u);
}
__device__ __forceinline__ float dec_f(unsigned k) {
    unsigned u = (k & 0x80000000u) ? (k & 0x7FFFFFFFu) : ~k;
    return __uint_as_float(u);
}
// enc(-inf) == 0x007FFFFF  (reset value)

__device__ __forceinline__ float block_max256(float v) {
    #pragma unroll
    for (int o = 16; o > 0; o >>= 1)
        v = fmaxf(v, __shfl_xor_sync(0xffffffffu, v, o));
    __shared__ float red[8];
    int w = threadIdx.x >> 5;
    if ((threadIdx.x & 31) == 0) red[w] = v;
    __syncthreads();
    if (threadIdx.x == 0) {
        #pragma unroll
        for (int i = 1; i < 8; i++) v = fmaxf(v, red[i]);
    }
    return v;  // valid on thread 0 only
}

// ---------------- reset per-replay state ----------------
__global__ void reset_k() {
    int i = threadIdx.x;
    if (i < Tn) { g_maxh[i] = 0x007FFFFFu; g_maxo[i] = 0x007FFFFFu; }
}

// ---------------- transpose spike_data [B][I][T] -> g_x [T][B][I] ----------------
__global__ void transpose_k(const float* __restrict__ sd) {
    __shared__ float tile[32][33];
    int b  = blockIdx.z;
    int i0 = blockIdx.y * 32;
    int t0 = blockIdx.x * 32;
    int tx = threadIdx.x, ty = threadIdx.y;
    #pragma unroll
    for (int j = 0; j < 32; j += 8) {
        int i = i0 + ty + j, t = t0 + tx;
        tile[ty + j][tx] = (t < Tn) ? sd[((size_t)b * In + i) * Tn + t] : 0.f;
    }
    __syncthreads();
    #pragma unroll
    for (int j = 0; j < 32; j += 8) {
        int t = t0 + ty + j, i = i0 + tx;
        if (t < Tn) g_x[((size_t)t * Bn + b) * In + i] = tile[tx][ty + j];
    }
}

// ---------------- GEMM1 partial: x_t[128,1024] @ w_hid[4096,1024]^T ----------------
// BM=BN=128, BK=16, TM=TN=8, 256 threads. grid = (Hn/128, 1, S1)
__global__ __launch_bounds__(256) void gemm1_k(const float* __restrict__ w_hid, int t) {
    __shared__ float As[16][132];
    __shared__ float Bs[16][132];
    const float* A = g_x + (size_t)t * Bn * In;
    const int n0    = blockIdx.x * 128;
    const int kbase = blockIdx.z * (In / S1);
    const int tid   = threadIdx.x;
    const int tm = (tid >> 4) << 3;
    const int tn = (tid & 15) << 3;
    float acc[8][8] = {};

    for (int kk = 0; kk < In / S1; kk += 16) {
        #pragma unroll
        for (int q = 0; q < 2; q++) {
            int fi  = tid + q * 256;       // 512 float4 loads per operand tile
            int row = fi >> 2;
            int kq  = (fi & 3) << 2;
            float4 av = *reinterpret_cast<const float4*>(&A[(size_t)row * In + kbase + kk + kq]);
            As[kq + 0][row] = av.x; As[kq + 1][row] = av.y;
            As[kq + 2][row] = av.z; As[kq + 3][row] = av.w;
            float4 bv = *reinterpret_cast<const float4*>(&w_hid[(size_t)(n0 + row) * In + kbase + kk + kq]);
            Bs[kq + 0][row] = bv.x; Bs[kq + 1][row] = bv.y;
            Bs[kq + 2][row] = bv.z; Bs[kq + 3][row] = bv.w;
        }
        __syncthreads();
        #pragma unroll
        for (int k = 0; k < 16; k++) {
            float a[8], b[8];
            *reinterpret_cast<float4*>(&a[0]) = *reinterpret_cast<const float4*>(&As[k][tm]);
            *reinterpret_cast<float4*>(&a[4]) = *reinterpret_cast<const float4*>(&As[k][tm + 4]);
            *reinterpret_cast<float4*>(&b[0]) = *reinterpret_cast<const float4*>(&Bs[k][tn]);
            *reinterpret_cast<float4*>(&b[4]) = *reinterpret_cast<const float4*>(&Bs[k][tn + 4]);
            #pragma unroll
            for (int i = 0; i < 8; i++)
                #pragma unroll
                for (int j = 0; j < 8; j++)
                    acc[i][j] = fmaf(a[i], b[j], acc[i][j]);
        }
        __syncthreads();
    }

    float* dst = g_p1 + (size_t)blockIdx.z * Bn * Hn;
    #pragma unroll
    for (int i = 0; i < 8; i++)
        #pragma unroll
        for (int j = 0; j < 8; j += 4) {
            float4 v = make_float4(acc[i][j], acc[i][j + 1], acc[i][j + 2], acc[i][j + 3]);
            *reinterpret_cast<float4*>(&dst[(size_t)(tm + i) * Hn + n0 + tn + j]) = v;
        }
}

// ---------------- fuse1: sum partials, membrane update, global max ----------------
__global__ __launch_bounds__(256) void fuse1_k(int t) {
    const bool  hp   = (t > 0);
    const float thrp = hp ? VTH * tanhf(GW * dec_f(g_maxh[t - 1])) : 0.f;
    constexpr int NF4 = Bn * Hn / 4;  // 131072
    float4* hv4 = reinterpret_cast<float4*>(g_hv);
    const float4* p14 = reinterpret_cast<const float4*>(g_p1);
    float lmax = -3.4e38f;
    for (int fi = blockIdx.x * blockDim.x + threadIdx.x; fi < NF4; fi += gridDim.x * blockDim.x) {
        float4 s = p14[fi];
        #pragma unroll
        for (int z = 1; z < S1; z++) {
            float4 p = p14[(size_t)z * NF4 + fi];
            s.x += p.x; s.y += p.y; s.z += p.z; s.w += p.w;
        }
        float4 ho = hp ? hv4[fi] : make_float4(0.f, 0.f, 0.f, 0.f);
        float4 hn;
        // hs in {0,1}; hv*0.5 is exact, so this matches the reference bit-for-bit up to the add
        hn.x = ho.x * ((hp && ho.x > thrp) ? 0.f : VDEC) + s.x;
        hn.y = ho.y * ((hp && ho.y > thrp) ? 0.f : VDEC) + s.y;
        hn.z = ho.z * ((hp && ho.z > thrp) ? 0.f : VDEC) + s.z;
        hn.w = ho.w * ((hp && ho.w > thrp) ? 0.f : VDEC) + s.w;
        hv4[fi] = hn;
        lmax = fmaxf(lmax, fmaxf(fmaxf(hn.x, hn.y), fmaxf(hn.z, hn.w)));
    }
    float bm = block_max256(lmax);
    if (threadIdx.x == 0) atomicMax(&g_maxh[t], enc_f(bm));
}

// ---------------- GEMM2 partial: hs_t[128,4096] @ w_out[512,4096]^T ----------------
// hs recomputed on the fly from g_hv and g_maxh[t]. grid = (On/128, 1, S2)
__global__ __launch_bounds__(256) void gemm2_k(const float* __restrict__ w_out, int t) {
    __shared__ float As[16][132];
    __shared__ float Bs[16][132];
    const float thr = VTH * tanhf(GW * dec_f(g_maxh[t]));
    const int n0    = blockIdx.x * 128;
    const int kbase = blockIdx.z * (Hn / S2);
    const int tid   = threadIdx.x;
    const int tm = (tid >> 4) << 3;
    const int tn = (tid & 15) << 3;
    float acc[8][8] = {};

    for (int kk = 0; kk < Hn / S2; kk += 16) {
        #pragma unroll
        for (int q = 0; q < 2; q++) {
            int fi  = tid + q * 256;
            int row = fi >> 2;
            int kq  = (fi & 3) << 2;
            float4 av = *reinterpret_cast<const float4*>(&g_hv[(size_t)row * Hn + kbase + kk + kq]);
            As[kq + 0][row] = (av.x > thr) ? 1.f : 0.f;
            As[kq + 1][row] = (av.y > thr) ? 1.f : 0.f;
            As[kq + 2][row] = (av.z > thr) ? 1.f : 0.f;
            As[kq + 3][row] = (av.w > thr) ? 1.f : 0.f;
            float4 bv = *reinterpret_cast<const float4*>(&w_out[(size_t)(n0 + row) * Hn + kbase + kk + kq]);
            Bs[kq + 0][row] = bv.x; Bs[kq + 1][row] = bv.y;
            Bs[kq + 2][row] = bv.z; Bs[kq + 3][row] = bv.w;
        }
        __syncthreads();
        #pragma unroll
        for (int k = 0; k < 16; k++) {
            float a[8], b[8];
            *reinterpret_cast<float4*>(&a[0]) = *reinterpret_cast<const float4*>(&As[k][tm]);
            *reinterpret_cast<float4*>(&a[4]) = *reinterpret_cast<const float4*>(&As[k][tm + 4]);
            *reinterpret_cast<float4*>(&b[0]) = *reinterpret_cast<const float4*>(&Bs[k][tn]);
            *reinterpret_cast<float4*>(&b[4]) = *reinterpret_cast<const float4*>(&Bs[k][tn + 4]);
            #pragma unroll
            for (int i = 0; i < 8; i++)
                #pragma unroll
                for (int j = 0; j < 8; j++)
                    acc[i][j] = fmaf(a[i], b[j], acc[i][j]);
        }
        __syncthreads();
    }

    float* dst = g_p2 + (size_t)blockIdx.z * Bn * On;
    #pragma unroll
    for (int i = 0; i < 8; i++)
        #pragma unroll
        for (int j = 0; j < 8; j += 4) {
            float4 v = make_float4(acc[i][j], acc[i][j + 1], acc[i][j + 2], acc[i][j + 3]);
            *reinterpret_cast<float4*>(&dst[(size_t)(tm + i) * On + n0 + tn + j]) = v;
        }
}

// ---------------- fuse2: sum partials, output membrane, accumulate prev spikes ----------------
__global__ __launch_bounds__(256) void fuse2_k(float* __restrict__ out, int t) {
    const bool  hp   = (t > 0);
    const float thrp = hp ? VTH * tanhf(GW * dec_f(g_maxo[t - 1])) : 0.f;
    constexpr int NF4 = Bn * On / 4;  // 16384
    int fi = blockIdx.x * 256 + threadIdx.x;  // grid = 64 blocks, exact cover
    const float4* p24 = reinterpret_cast<const float4*>(g_p2);
    float4* ov4 = reinterpret_cast<float4*>(g_ov);
    float4* o4  = reinterpret_cast<float4*>(out);

    float4 s = p24[fi];
    #pragma unroll
    for (int z = 1; z < S2; z++) {
        float4 p = p24[(size_t)z * NF4 + fi];
        s.x += p.x; s.y += p.y; s.z += p.z; s.w += p.w;
    }
    float4 oo = hp ? ov4[fi] : make_float4(0.f, 0.f, 0.f, 0.f);
    float4 os;
    os.x = (hp && oo.x > thrp) ? 1.f : 0.f;
    os.y = (hp && oo.y > thrp) ? 1.f : 0.f;
    os.z = (hp && oo.z > thrp) ? 1.f : 0.f;
    os.w = (hp && oo.w > thrp) ? 1.f : 0.f;
    float4 acc = hp ? o4[fi] : make_float4(0.f, 0.f, 0.f, 0.f);
    acc.x += os.x; acc.y += os.y; acc.z += os.z; acc.w += os.w;
    o4[fi] = acc;
    float4 nv;
    nv.x = oo.x * ((os.x > 0.f) ? 0.f : VDEC) + s.x;
    nv.y = oo.y * ((os.y > 0.f) ? 0.f : VDEC) + s.y;
    nv.z = oo.z * ((os.z > 0.f) ? 0.f : VDEC) + s.z;
    nv.w = oo.w * ((os.w > 0.f) ? 0.f : VDEC) + s.w;
    ov4[fi] = nv;
    float lmax = fmaxf(fmaxf(nv.x, nv.y), fmaxf(nv.z, nv.w));
    float bm = block_max256(lmax);
    if (threadIdx.x == 0) atomicMax(&g_maxo[t], enc_f(bm));
}

// ---------------- final: accumulate last step's output spikes ----------------
__global__ __launch_bounds__(256) void final_k(float* __restrict__ out) {
    const float thr = VTH * tanhf(GW * dec_f(g_maxo[Tn - 1]));
    int fi = blockIdx.x * 256 + threadIdx.x;  // 64 blocks
    float4 ov = reinterpret_cast<const float4*>(g_ov)[fi];
    float4 o  = reinterpret_cast<float4*>(out)[fi];
    o.x += (ov.x > thr) ? 1.f : 0.f;
    o.y += (ov.y > thr) ? 1.f : 0.f;
    o.z += (ov.z > thr) ? 1.f : 0.f;
    o.w += (ov.w > thr) ? 1.f : 0.f;
    reinterpret_cast<float4*>(out)[fi] = o;
}

// ---------------- launch ----------------
extern "C" void kernel_launch(void* const* d_in, const int* in_sizes, int n_in,
                              void* d_out, int out_size) {
    const float* sd    = (const float*)d_in[0];  // spike_data [B][I][T]
    const float* w_hid = (const float*)d_in[5];  // [H][I]
    const float* w_out = (const float*)d_in[6];  // [O][H]
    float* out = (float*)d_out;                  // [B][O]

    reset_k<<<1, 128>>>();
    transpose_k<<<dim3((Tn + 31) / 32, In / 32, Bn), dim3(32, 8)>>>(sd);

    for (int t = 0; t < Tn; t++) {
        gemm1_k<<<dim3(Hn / 128, 1, S1), 256>>>(w_hid, t);
        fuse1_k<<<128, 256>>>(t);
        gemm2_k<<<dim3(On / 128, 1, S2), 256>>>(w_out, t);
        fuse2_k<<<64, 256>>>(out, t);
    }
    final_k<<<64, 256>>>(out);
}

// round 5
// speedup vs baseline: 1.5879x; 1.5879x over previous
#include <cuda_runtime.h>
#include <cuda_bf16.h>
#include <cstdint>

// ---------------- problem constants ----------------
constexpr int Bn = 128;   // batch (GEMM M)
constexpr int In = 1024;  // input features
constexpr int Hn = 4096;  // hidden
constexpr int On = 512;   // output
constexpr int Tn = 100;   // timesteps
// GEMM1: 3-term split, 6 kept products: A [a0|a1|a2|a0|a1|a0] x W [w0|w0|w0|w1|w1|w2]
constexpr int K1 = 6 * In;   // 6144
// GEMM2: spikes exact, 3-term weight split: A [s|s|s] x W [w0|w1|w2]
constexpr int K2 = 3 * Hn;   // 12288
constexpr int S1 = 4;        // k-splits GEMM1 -> 1536/CTA -> 24 chunks of 64
constexpr int S2 = 32;       // k-splits GEMM2 -> 384/CTA  -> 6 chunks of 64
constexpr int C1 = K1 / S1 / 64;  // 24
constexpr int C2 = K2 / S2 / 64;  // 6
constexpr int STAGES = 4;    // cp.async pipeline depth
constexpr int STAGE_BYTES = 32768;               // A tile 16KB + B tile 16KB
constexpr int SMEM_BYTES = STAGES * STAGE_BYTES; // 128KB

constexpr float VDEC = 0.5f;
constexpr float VTH  = 0.3f;
constexpr float GW   = 0.3f;

// ---------------- device scratch ----------------
__device__ __nv_bfloat16 g_a1[(size_t)Tn * Bn * K1];  // [T][B][6144] split input  157MB
__device__ __nv_bfloat16 g_w1[(size_t)Hn * K1];       // [H][6144]  50MB
__device__ __nv_bfloat16 g_w2[(size_t)On * K2];       // [O][12288] 12.6MB
__device__ __nv_bfloat16 g_hs[(size_t)Bn * Hn];       // hidden spikes bf16
__device__ float    g_hv[Bn * Hn];
__device__ float    g_ov[Bn * On];
__device__ float    g_p1[(size_t)S1 * Bn * Hn];       // GEMM1 partials
__device__ float    g_p2[(size_t)S2 * Bn * On];       // GEMM2 partials
__device__ unsigned g_maxh[Tn];
__device__ unsigned g_maxo[Tn];

// ---------------- helpers ----------------
__device__ __forceinline__ unsigned enc_f(float x) {
    unsigned u = __float_as_uint(x);
    return (u & 0x80000000u) ? ~u : (u | 0x80000000u);
}
__device__ __forceinline__ float dec_f(unsigned k) {
    unsigned u = (k & 0x80000000u) ? (k & 0x7FFFFFFFu) : ~k;
    return __uint_as_float(u);
}
__device__ __forceinline__ float block_max256(float v) {
    #pragma unroll
    for (int o = 16; o > 0; o >>= 1)
        v = fmaxf(v, __shfl_xor_sync(0xffffffffu, v, o));
    __shared__ float red[8];
    int w = threadIdx.x >> 5;
    if ((threadIdx.x & 31) == 0) red[w] = v;
    __syncthreads();
    if (threadIdx.x == 0) {
        #pragma unroll
        for (int i = 1; i < 8; i++) v = fmaxf(v, red[i]);
    }
    return v;
}
__device__ __forceinline__ uint32_t smem_to_u32(const void* p) {
    uint32_t a;
    asm("{ .reg .u64 t; cvta.to.shared.u64 t, %1; cvt.u32.u64 %0, t; }" : "=r"(a) : "l"(p));
    return a;
}

#define LDSM_X4(r0, r1, r2, r3, addr) \
    asm volatile("ldmatrix.sync.aligned.m8n8.x4.shared.b16 {%0,%1,%2,%3}, [%4];" \
        : "=r"(r0), "=r"(r1), "=r"(r2), "=r"(r3) : "r"(addr))

#define MMA16816(d, a, b0, b1) \
    asm volatile("mma.sync.aligned.m16n8k16.row.col.f32.bf16.bf16.f32 " \
        "{%0,%1,%2,%3}, {%4,%5,%6,%7}, {%8,%9}, {%0,%1,%2,%3};" \
        : "+f"((d)[0]), "+f"((d)[1]), "+f"((d)[2]), "+f"((d)[3]) \
        : "r"((a)[0]), "r"((a)[1]), "r"((a)[2]), "r"((a)[3]), "r"(b0), "r"(b1))

#define CP_ASYNC16(sdst, gsrc) \
    asm volatile("cp.async.cg.shared.global [%0], [%1], 16;" :: "r"(sdst), "l"(gsrc) : "memory")
#define CP_COMMIT() asm volatile("cp.async.commit_group;" ::: "memory")
#define CP_WAIT(n)  asm volatile("cp.async.wait_group %0;" :: "n"(n) : "memory")

// load 128 rows x 64 bf16 tile (128B rows, SW128 swizzle) via cp.async
__device__ __forceinline__ void cp_tile(uint32_t sdst, const __nv_bfloat16* __restrict__ src, int ld) {
    int tid = threadIdx.x;
    #pragma unroll
    for (int p = 0; p < 4; p++) {
        int id  = p * 256 + tid;   // 1024 16B granules
        int row = id >> 3, g = id & 7;
        uint32_t off = (uint32_t)(row * 128 + g * 16);
        off ^= (off >> 3) & 0x70u;
        CP_ASYNC16(sdst + off, src + (size_t)row * ld + g * 8);
    }
}

// ---------------- HMMA GEMM: D[128, 128-tile] partial over this CTA's K range ----------------
// grid.x = N/128 tiles, grid.y = k-split z. 256 threads = 8 warps (2m x 4n), warp tile 64x32.
template <int NCHUNK, bool SPIKE>
__global__ void __launch_bounds__(256, 1) gemm_hmma_k(int t) {
    extern __shared__ char smem[];
    const uint32_t sbase = smem_to_u32(smem);
    const int tid  = threadIdx.x;
    const int wid  = tid >> 5, lane = tid & 31;
    const int wm   = wid & 1, wn = wid >> 1;       // 2 x 4 warp grid
    const int n0   = blockIdx.x * 128;
    const int z    = blockIdx.y;

    const __nv_bfloat16* A = SPIKE ? g_hs : (g_a1 + (size_t)t * Bn * K1);
    const int lda   = SPIKE ? Hn : K1;
    const int amask = SPIKE ? (Hn - 1) : 0x7FFFFFFF;
    const __nv_bfloat16* W = SPIKE ? g_w2 : g_w1;
    const int ldw = SPIKE ? K2 : K1;
    const int ldo = SPIKE ? On : Hn;
    float* P = (SPIKE ? g_p2 : g_p1) + (size_t)z * Bn * ldo + n0;
    const int k0 = z * NCHUNK * 64;

    // ldmatrix per-lane addressing
    const int grp = lane >> 3, lrow = lane & 7;
    const int a_row = lrow + ((grp & 1) << 3);
    const uint32_t a_kb = (uint32_t)((grp >> 1) << 4);
    const int b_row = lrow + ((grp >> 1) << 3);
    const uint32_t b_kb = (uint32_t)((grp & 1) << 4);

    uint32_t aRB[4], aXR[4], bRB[2], bXR[2];
    #pragma unroll
    for (int mf = 0; mf < 4; mf++) {
        uint32_t rb = (uint32_t)((wm * 64 + mf * 16 + a_row) * 128);
        aRB[mf] = rb; aXR[mf] = (rb >> 3) & 0x70u;
    }
    #pragma unroll
    for (int pf = 0; pf < 2; pf++) {
        uint32_t rb = (uint32_t)((wn * 32 + pf * 16 + b_row) * 128);
        bRB[pf] = rb; bXR[pf] = (rb >> 3) & 0x70u;
    }

    float d[4][4][4] = {};

    auto issue = [&](int c) {
        if (c < NCHUNK) {
            uint32_t st = sbase + (uint32_t)(c % STAGES) * (uint32_t)STAGE_BYTES;
            int kk = k0 + c * 64;
            cp_tile(st,          A + (kk & amask), lda);
            cp_tile(st + 16384u, W + (size_t)n0 * ldw + kk, ldw);
        }
        CP_COMMIT();
    };

    #pragma unroll
    for (int c = 0; c < STAGES - 1; c++) issue(c);

    #pragma unroll 1
    for (int c = 0; c < NCHUNK; c++) {
        CP_WAIT(2);
        __syncthreads();
        issue(c + STAGES - 1);

        const uint32_t sA = sbase + (uint32_t)(c % STAGES) * (uint32_t)STAGE_BYTES;
        const uint32_t sB = sA + 16384u;
        #pragma unroll
        for (int kk = 0; kk < 4; kk++) {
            const uint32_t ck = (uint32_t)(kk << 5);
            uint32_t a[4][4];
            #pragma unroll
            for (int mf = 0; mf < 4; mf++)
                LDSM_X4(a[mf][0], a[mf][1], a[mf][2], a[mf][3],
                        sA + aRB[mf] + ((ck + a_kb) ^ aXR[mf]));
            uint32_t b[4][2];
            #pragma unroll
            for (int pf = 0; pf < 2; pf++) {
                uint32_t r0, r1, r2, r3;
                LDSM_X4(r0, r1, r2, r3, sB + bRB[pf] + ((ck + b_kb) ^ bXR[pf]));
                b[2 * pf][0] = r0; b[2 * pf][1] = r1;
                b[2 * pf + 1][0] = r2; b[2 * pf + 1][1] = r3;
            }
            #pragma unroll
            for (int mf = 0; mf < 4; mf++)
                #pragma unroll
                for (int nf = 0; nf < 4; nf++)
                    MMA16816(d[mf][nf], a[mf], b[nf][0], b[nf][1]);
        }
    }
    CP_WAIT(0);

    // epilogue
    const int r0 = lane >> 2, c0 = (lane & 3) * 2;
    #pragma unroll
    for (int mf = 0; mf < 4; mf++) {
        #pragma unroll
        for (int nf = 0; nf < 4; nf++) {
            int m = wm * 64 + mf * 16 + r0;
            int n = wn * 32 + nf * 8 + c0;
            *reinterpret_cast<float2*>(&P[(size_t)m * ldo + n]) =
                make_float2(d[mf][nf][0], d[mf][nf][1]);
            *reinterpret_cast<float2*>(&P[(size_t)(m + 8) * ldo + n]) =
                make_float2(d[mf][nf][2], d[mf][nf][3]);
        }
    }
}

// ---------------- prep kernels ----------------
__global__ void reset_k() {
    int i = threadIdx.x;
    if (i < Tn) { g_maxh[i] = 0x007FFFFFu; g_maxo[i] = 0x007FFFFFu; }
}

// 3-term bf16 split (exact residuals in fp32)
__device__ __forceinline__ void split3(float v, __nv_bfloat16& s0, __nv_bfloat16& s1, __nv_bfloat16& s2) {
    s0 = __float2bfloat16(v);
    float r1 = v - __bfloat162float(s0);
    s1 = __float2bfloat16(r1);
    float r2 = r1 - __bfloat162float(s1);
    s2 = __float2bfloat16(r2);
}

// spike_data [B][I][T] fp32 -> g_a1 [T][B][ a0|a1|a2|a0|a1|a0 ] (6x1024 bf16)
__global__ void prep_a1_k(const float* __restrict__ sd) {
    __shared__ float tile[32][33];
    int b = blockIdx.z, i0 = blockIdx.y * 32, t0 = blockIdx.x * 32;
    int tx = threadIdx.x, ty = threadIdx.y;
    #pragma unroll
    for (int j = 0; j < 32; j += 8) {
        int i = i0 + ty + j, tt = t0 + tx;
        tile[ty + j][tx] = (tt < Tn) ? sd[((size_t)b * In + i) * Tn + tt] : 0.f;
    }
    __syncthreads();
    #pragma unroll
    for (int j = 0; j < 32; j += 8) {
        int tt = t0 + ty + j, i = i0 + tx;
        if (tt < Tn) {
            __nv_bfloat16 a0, a1, a2;
            split3(tile[tx][ty + j], a0, a1, a2);
            size_t base = ((size_t)tt * Bn + b) * K1;
            g_a1[base + 0 * In + i] = a0;
            g_a1[base + 1 * In + i] = a1;
            g_a1[base + 2 * In + i] = a2;
            g_a1[base + 3 * In + i] = a0;
            g_a1[base + 4 * In + i] = a1;
            g_a1[base + 5 * In + i] = a0;
        }
    }
}

// w_hid [H][1024] -> g_w1 [H][ w0|w0|w0|w1|w1|w2 ]
__global__ void conv_w1_k(const float* __restrict__ w) {
    int idx = blockIdx.x * 256 + threadIdx.x;  // exact Hn*In
    __nv_bfloat16 w0, w1, w2;
    split3(w[idx], w0, w1, w2);
    int h = idx >> 10, k = idx & 1023;
    size_t base = (size_t)h * K1;
    g_w1[base + 0 * In + k] = w0;
    g_w1[base + 1 * In + k] = w0;
    g_w1[base + 2 * In + k] = w0;
    g_w1[base + 3 * In + k] = w1;
    g_w1[base + 4 * In + k] = w1;
    g_w1[base + 5 * In + k] = w2;
}
// w_out [O][4096] -> g_w2 [O][ w0|w1|w2 ]
__global__ void conv_w2_k(const float* __restrict__ w) {
    int idx = blockIdx.x * 256 + threadIdx.x;  // exact On*Hn
    __nv_bfloat16 w0, w1, w2;
    split3(w[idx], w0, w1, w2);
    int o = idx >> 12, k = idx & 4095;
    size_t base = (size_t)o * K2;
    g_w2[base + 0 * Hn + k] = w0;
    g_w2[base + 1 * Hn + k] = w1;
    g_w2[base + 2 * Hn + k] = w2;
}

// ---------------- fuse1: sum partials, membrane update, global max ----------------
__global__ __launch_bounds__(256) void fuse1_k(int t) {
    const bool  hp   = (t > 0);
    const float thrp = hp ? VTH * tanhf(GW * dec_f(g_maxh[t - 1])) : 0.f;
    constexpr int NF4 = Bn * Hn / 4;
    float4* hv4 = reinterpret_cast<float4*>(g_hv);
    const float4* p14 = reinterpret_cast<const float4*>(g_p1);
    float lmax = -3.4e38f;
    for (int fi = blockIdx.x * blockDim.x + threadIdx.x; fi < NF4; fi += gridDim.x * blockDim.x) {
        float4 s = p14[fi];
        #pragma unroll
        for (int zz = 1; zz < S1; zz++) {
            float4 p = p14[(size_t)zz * NF4 + fi];
            s.x += p.x; s.y += p.y; s.z += p.z; s.w += p.w;
        }
        float4 ho = hp ? hv4[fi] : make_float4(0.f, 0.f, 0.f, 0.f);
        float4 hn;
        hn.x = ho.x * ((hp && ho.x > thrp) ? 0.f : VDEC) + s.x;
        hn.y = ho.y * ((hp && ho.y > thrp) ? 0.f : VDEC) + s.y;
        hn.z = ho.z * ((hp && ho.z > thrp) ? 0.f : VDEC) + s.z;
        hn.w = ho.w * ((hp && ho.w > thrp) ? 0.f : VDEC) + s.w;
        hv4[fi] = hn;
        lmax = fmaxf(lmax, fmaxf(fmaxf(hn.x, hn.y), fmaxf(hn.z, hn.w)));
    }
    float bm = block_max256(lmax);
    if (threadIdx.x == 0) atomicMax(&g_maxh[t], enc_f(bm));
}

// ---------------- spike: hv -> bf16 spikes ----------------
__global__ __launch_bounds__(256) void spike_k(int t) {
    const float thr = VTH * tanhf(GW * dec_f(g_maxh[t]));
    int i = blockIdx.x * 256 + threadIdx.x;  // 512 blocks, exact cover of Bn*Hn/4
    float4 v = reinterpret_cast<const float4*>(g_hv)[i];
    uint32_t lo = (v.x > thr ? 0x3F80u : 0u) | (v.y > thr ? 0x3F800000u : 0u);
    uint32_t hi = (v.z > thr ? 0x3F80u : 0u) | (v.w > thr ? 0x3F800000u : 0u);
    reinterpret_cast<uint2*>(g_hs)[i] = make_uint2(lo, hi);
}

// ---------------- fuse2: sum partials, output membrane, accumulate prev spikes ----------------
__global__ __launch_bounds__(256) void fuse2_k(float* __restrict__ out, int t) {
    const bool  hp   = (t > 0);
    const float thrp = hp ? VTH * tanhf(GW * dec_f(g_maxo[t - 1])) : 0.f;
    constexpr int NF4 = Bn * On / 4;
    int fi = blockIdx.x * 256 + threadIdx.x;  // 64 blocks exact
    const float4* p24 = reinterpret_cast<const float4*>(g_p2);
    float4* ov4 = reinterpret_cast<float4*>(g_ov);
    float4* o4  = reinterpret_cast<float4*>(out);

    float4 s = p24[fi];
    #pragma unroll
    for (int zz = 1; zz < S2; zz++) {
        float4 p = p24[(size_t)zz * NF4 + fi];
        s.x += p.x; s.y += p.y; s.z += p.z; s.w += p.w;
    }
    float4 oo = hp ? ov4[fi] : make_float4(0.f, 0.f, 0.f, 0.f);
    float4 os;
    os.x = (hp && oo.x > thrp) ? 1.f : 0.f;
    os.y = (hp && oo.y > thrp) ? 1.f : 0.f;
    os.z = (hp && oo.z > thrp) ? 1.f : 0.f;
    os.w = (hp && oo.w > thrp) ? 1.f : 0.f;
    float4 acc = hp ? o4[fi] : make_float4(0.f, 0.f, 0.f, 0.f);
    acc.x += os.x; acc.y += os.y; acc.z += os.z; acc.w += os.w;
    o4[fi] = acc;
    float4 nv;
    nv.x = oo.x * ((os.x > 0.f) ? 0.f : VDEC) + s.x;
    nv.y = oo.y * ((os.y > 0.f) ? 0.f : VDEC) + s.y;
    nv.z = oo.z * ((os.z > 0.f) ? 0.f : VDEC) + s.z;
    nv.w = oo.w * ((os.w > 0.f) ? 0.f : VDEC) + s.w;
    ov4[fi] = nv;
    float lmax = fmaxf(fmaxf(nv.x, nv.y), fmaxf(nv.z, nv.w));
    float bm = block_max256(lmax);
    if (threadIdx.x == 0) atomicMax(&g_maxo[t], enc_f(bm));
}

__global__ __launch_bounds__(256) void final_k(float* __restrict__ out) {
    const float thr = VTH * tanhf(GW * dec_f(g_maxo[Tn - 1]));
    int fi = blockIdx.x * 256 + threadIdx.x;  // 64 blocks
    float4 ov = reinterpret_cast<const float4*>(g_ov)[fi];
    float4 o  = reinterpret_cast<float4*>(out)[fi];
    o.x += (ov.x > thr) ? 1.f : 0.f;
    o.y += (ov.y > thr) ? 1.f : 0.f;
    o.z += (ov.z > thr) ? 1.f : 0.f;
    o.w += (ov.w > thr) ? 1.f : 0.f;
    reinterpret_cast<float4*>(out)[fi] = o;
}

// ---------------- launch ----------------
extern "C" void kernel_launch(void* const* d_in, const int* in_sizes, int n_in,
                              void* d_out, int out_size) {
    const float* sd    = (const float*)d_in[0];  // spike_data [B][I][T]
    const float* w_hid = (const float*)d_in[5];  // [H][I]
    const float* w_out = (const float*)d_in[6];  // [O][H]
    float* out = (float*)d_out;                  // [B][O]

    cudaFuncSetAttribute((const void*)gemm_hmma_k<C1, false>,
                         cudaFuncAttributeMaxDynamicSharedMemorySize, SMEM_BYTES);
    cudaFuncSetAttribute((const void*)gemm_hmma_k<C2, true>,
                         cudaFuncAttributeMaxDynamicSharedMemorySize, SMEM_BYTES);

    reset_k<<<1, 128>>>();
    prep_a1_k<<<dim3((Tn + 31) / 32, In / 32, Bn), dim3(32, 8)>>>(sd);
    conv_w1_k<<<Hn * In / 256, 256>>>(w_hid);
    conv_w2_k<<<On * Hn / 256, 256>>>(w_out);

    for (int t = 0; t < Tn; t++) {
        gemm_hmma_k<C1, false><<<dim3(Hn / 128, S1), 256, SMEM_BYTES>>>(t);
        fuse1_k<<<512, 256>>>(t);
        spike_k<<<512, 256>>>(t);
        gemm_hmma_k<C2, true><<<dim3(On / 128, S2), 256, SMEM_BYTES>>>(t);
        fuse2_k<<<64, 256>>>(out, t);
    }
    final_k<<<64, 256>>>(out);
}